// round 1
// baseline (speedup 1.0000x reference)
#include <cuda_runtime.h>
#include <math.h>

#define NPTS 40000
#define SNBR 16
#define CDIM 96
#define GDIM 12
#define EPSF 1e-5f

// Scratch for projected features (device globals: no allocation allowed)
__device__ float g_query[NPTS * CDIM];
__device__ float g_keyf [NPTS * CDIM];
__device__ float g_val  [NPTS * CDIM];

__device__ __forceinline__ float warp_sum32(float v) {
    v += __shfl_xor_sync(0xffffffffu, v, 16);
    v += __shfl_xor_sync(0xffffffffu, v, 8);
    v += __shfl_xor_sync(0xffffffffu, v, 4);
    v += __shfl_xor_sync(0xffffffffu, v, 2);
    v += __shfl_xor_sync(0xffffffffu, v, 1);
    return v;
}
__device__ __forceinline__ float group_sum16(float v) {
    v += __shfl_xor_sync(0xffffffffu, v, 8);
    v += __shfl_xor_sync(0xffffffffu, v, 4);
    v += __shfl_xor_sync(0xffffffffu, v, 2);
    v += __shfl_xor_sync(0xffffffffu, v, 1);
    return v;
}

// ---------------------------------------------------------------------------
// Kernel A: fused q/k/v projections.  query = relu(ln(q@Wq+bq)), same for k,
// val = v@Wv+bv.  Weights transposed in smem, row stride 100 floats so each
// lane reads its output-channel row with conflict-free LDS.128.
// ---------------------------------------------------------------------------
template <bool DO_LN>
__device__ __forceinline__ void project_row(
    const float* __restrict__ src, float* __restrict__ dst,
    const float* Wt,            // smem, [c][100]
    const float* bias, const float* gain, const float* beta, // smem
    float* xb,                  // per-warp smem stage, 96 floats
    int row, int lane)
{
    const int c0 = lane, c1 = lane + 32, c2 = lane + 64;
    // stage input row
    xb[c0] = src[row * CDIM + c0];
    xb[c1] = src[row * CDIM + c1];
    xb[c2] = src[row * CDIM + c2];
    __syncwarp();
    const float4* xb4 = (const float4*)xb;
    const float4* W0 = (const float4*)(Wt + c0 * 100);
    const float4* W1 = (const float4*)(Wt + c1 * 100);
    const float4* W2 = (const float4*)(Wt + c2 * 100);
    float a0x=0,a0y=0,a0z=0,a0w=0, a1x=0,a1y=0,a1z=0,a1w=0, a2x=0,a2y=0,a2z=0,a2w=0;
#pragma unroll
    for (int j4 = 0; j4 < 24; j4++) {
        float4 xv = xb4[j4];
        float4 u0 = W0[j4];
        a0x = fmaf(u0.x, xv.x, a0x); a0y = fmaf(u0.y, xv.y, a0y);
        a0z = fmaf(u0.z, xv.z, a0z); a0w = fmaf(u0.w, xv.w, a0w);
        float4 u1 = W1[j4];
        a1x = fmaf(u1.x, xv.x, a1x); a1y = fmaf(u1.y, xv.y, a1y);
        a1z = fmaf(u1.z, xv.z, a1z); a1w = fmaf(u1.w, xv.w, a1w);
        float4 u2 = W2[j4];
        a2x = fmaf(u2.x, xv.x, a2x); a2y = fmaf(u2.y, xv.y, a2y);
        a2z = fmaf(u2.z, xv.z, a2z); a2w = fmaf(u2.w, xv.w, a2w);
    }
    __syncwarp();
    float y0 = a0x + a0y + a0z + a0w + bias[c0];
    float y1 = a1x + a1y + a1z + a1w + bias[c1];
    float y2 = a2x + a2y + a2z + a2w + bias[c2];
    if (DO_LN) {
        float mu = warp_sum32(y0 + y1 + y2) * (1.0f / 96.0f);
        float d0 = y0 - mu, d1 = y1 - mu, d2 = y2 - mu;
        float var = warp_sum32(d0*d0 + d1*d1 + d2*d2) * (1.0f / 96.0f);
        float rs = rsqrtf(var + EPSF);
        y0 = fmaxf(fmaf(d0 * rs, gain[c0], beta[c0]), 0.0f);
        y1 = fmaxf(fmaf(d1 * rs, gain[c1], beta[c1]), 0.0f);
        y2 = fmaxf(fmaf(d2 * rs, gain[c2], beta[c2]), 0.0f);
    }
    dst[row * CDIM + c0] = y0;
    dst[row * CDIM + c1] = y1;
    dst[row * CDIM + c2] = y2;
}

__global__ void __launch_bounds__(256, 1) proj_kernel(
    const float* __restrict__ q, const float* __restrict__ k, const float* __restrict__ v,
    const float* __restrict__ Wq, const float* __restrict__ bq,
    const float* __restrict__ gq, const float* __restrict__ betaq,
    const float* __restrict__ Wk, const float* __restrict__ bk,
    const float* __restrict__ gk, const float* __restrict__ betak,
    const float* __restrict__ Wv, const float* __restrict__ bv)
{
    extern __shared__ float sm[];
    float* Wt  = sm;                // 3 * 9600
    float* prm = sm + 28800;        // bq,gq,betaq | bk,gk,betak | bv  (7*96)
    float* xst = sm + 28800 + 672;  // 8 warps * 96

    int tid = threadIdx.x;
    for (int i = tid; i < 9216; i += blockDim.x) {
        int j = i / 96, c = i % 96;
        Wt[0 * 9600 + c * 100 + j] = Wq[i];
        Wt[1 * 9600 + c * 100 + j] = Wk[i];
        Wt[2 * 9600 + c * 100 + j] = Wv[i];
    }
    for (int i = tid; i < 96; i += blockDim.x) {
        prm[i]       = bq[i];  prm[96 + i]  = gq[i];  prm[192 + i] = betaq[i];
        prm[288 + i] = bk[i];  prm[384 + i] = gk[i];  prm[480 + i] = betak[i];
        prm[576 + i] = bv[i];
    }
    __syncthreads();

    int warp = tid >> 5, lane = tid & 31;
    int gwarp = blockIdx.x * 8 + warp;
    int nwarp = gridDim.x * 8;
    float* xb = xst + warp * 96;

    for (int row = gwarp; row < NPTS; row += nwarp) {
        project_row<true >(q, g_query, Wt,          prm,       prm + 96,  prm + 192, xb, row, lane);
        project_row<true >(k, g_keyf,  Wt + 9600,   prm + 288, prm + 384, prm + 480, xb, row, lane);
        project_row<false>(v, g_val,   Wt + 19200,  prm + 576, prm,       prm,       xb, row, lane);
    }
}

// ---------------------------------------------------------------------------
// Kernel B: fused grouped vector attention. One block handles points (grid-
// stride). 4 warps x 4 neighbor pairs. All weights resident in smem.
// ---------------------------------------------------------------------------
// smem float offsets
#define OFF_WP2T   0        // 9600  (transposed, [c][100])
#define OFF_WW1T   9600     // 1200  (transposed, [g][100])
#define OFF_WP1    10800    // 288
#define OFF_BP1    11088    // 96
#define OFF_GP     11184    // 96
#define OFF_BETAP  11280    // 96
#define OFF_BP2    11376    // 96
#define OFF_WW2    11472    // 144
#define OFF_BW1    11616    // 12
#define OFF_GW     11628    // 12
#define OFF_BETAW  11640    // 12
#define OFF_BW2    11652    // 12
#define OFF_QROW   11664    // 96
#define OFF_VP     11760    // 16*96
#define OFF_WLOG   13296    // 16*12
#define OFF_MBUF   13488    // 16
#define OFF_HBUF   13504    // 4*96
#define SMEMB_FLOATS 13888

__global__ void __launch_bounds__(128, 4) attn_kernel(
    const float* __restrict__ xyz, const int* __restrict__ refidx,
    const float* __restrict__ Wp1, const float* __restrict__ bp1,
    const float* __restrict__ gp,  const float* __restrict__ betap,
    const float* __restrict__ Wp2, const float* __restrict__ bp2,
    const float* __restrict__ Ww1, const float* __restrict__ bw1,
    const float* __restrict__ gw,  const float* __restrict__ betaw,
    const float* __restrict__ Ww2, const float* __restrict__ bw2,
    float* __restrict__ out)
{
    extern __shared__ float sm[];
    float* Wp2t  = sm + OFF_WP2T;
    float* Ww1t  = sm + OFF_WW1T;
    float* sWp1  = sm + OFF_WP1;
    float* sbp1  = sm + OFF_BP1;
    float* sgp   = sm + OFF_GP;
    float* sbetap= sm + OFF_BETAP;
    float* sbp2  = sm + OFF_BP2;
    float* sWw2  = sm + OFF_WW2;
    float* sbw1  = sm + OFF_BW1;
    float* sgw   = sm + OFF_GW;
    float* sbetaw= sm + OFF_BETAW;
    float* sbw2  = sm + OFF_BW2;
    float* qrow  = sm + OFF_QROW;
    float* vp    = sm + OFF_VP;
    float* wlog  = sm + OFF_WLOG;
    float* mbuf  = sm + OFF_MBUF;
    float* hbuf  = sm + OFF_HBUF;

    int tid = threadIdx.x;
    for (int i = tid; i < 9216; i += blockDim.x) {
        int j = i / 96, c = i % 96;
        Wp2t[c * 100 + j] = Wp2[i];
    }
    for (int i = tid; i < 1152; i += blockDim.x) {
        int j = i / 12, g = i % 12;
        Ww1t[g * 100 + j] = Ww1[i];
    }
    for (int i = tid; i < 288; i += blockDim.x) sWp1[i] = Wp1[i];
    for (int i = tid; i < 96; i += blockDim.x) {
        sbp1[i] = bp1[i]; sgp[i] = gp[i]; sbetap[i] = betap[i]; sbp2[i] = bp2[i];
    }
    for (int i = tid; i < 144; i += blockDim.x) sWw2[i] = Ww2[i];
    if (tid < 12) { sbw1[tid] = bw1[tid]; sgw[tid] = gw[tid]; sbetaw[tid] = betaw[tid]; sbw2[tid] = bw2[tid]; }
    __syncthreads();

    int warp = tid >> 5, lane = tid & 31;
    const int c0 = lane, c1 = lane + 32, c2 = lane + 64;
    float* hb = hbuf + warp * 96;
    const float4* hb4 = (const float4*)hb;
    const float4* W0 = (const float4*)(Wp2t + c0 * 100);
    const float4* W1 = (const float4*)(Wp2t + c1 * 100);
    const float4* W2 = (const float4*)(Wp2t + c2 * 100);

    for (int n = blockIdx.x; n < NPTS; n += gridDim.x) {
        __syncthreads();   // previous point's phase-2 readers done
        if (tid < 96) qrow[tid] = g_query[n * CDIM + tid];
        __syncthreads();

        float px = xyz[n * 3], py = xyz[n * 3 + 1], pz = xyz[n * 3 + 2];

        for (int ss = 0; ss < 4; ss++) {
            int s = warp * 4 + ss;
            int idx = refidx[n * SNBR + s];
            float mk = (idx >= 0) ? 1.0f : 0.0f;
            int safe = (idx >= 0) ? idx : 0;
            float p0 = (xyz[safe * 3]     - px) * mk;
            float p1 = (xyz[safe * 3 + 1] - py) * mk;
            float p2 = (xyz[safe * 3 + 2] - pz) * mk;

            // prefetch gathers (L2 hits) early to hide latency behind matvec
            float kg0 = g_keyf[safe * CDIM + c0];
            float kg1 = g_keyf[safe * CDIM + c1];
            float kg2 = g_keyf[safe * CDIM + c2];
            float vg0 = g_val [safe * CDIM + c0];
            float vg1 = g_val [safe * CDIM + c1];
            float vg2 = g_val [safe * CDIM + c2];

            // p-bias layer 1: pos @ Wp1 + bp1  -> LN -> relu
            float t0 = fmaf(p0, sWp1[c0], fmaf(p1, sWp1[96 + c0], fmaf(p2, sWp1[192 + c0], sbp1[c0])));
            float t1 = fmaf(p0, sWp1[c1], fmaf(p1, sWp1[96 + c1], fmaf(p2, sWp1[192 + c1], sbp1[c1])));
            float t2 = fmaf(p0, sWp1[c2], fmaf(p1, sWp1[96 + c2], fmaf(p2, sWp1[192 + c2], sbp1[c2])));
            float mu = warp_sum32(t0 + t1 + t2) * (1.0f / 96.0f);
            float d0 = t0 - mu, d1 = t1 - mu, d2 = t2 - mu;
            float var = warp_sum32(d0 * d0 + d1 * d1 + d2 * d2) * (1.0f / 96.0f);
            float rs = rsqrtf(var + EPSF);
            float h0 = fmaxf(fmaf(d0 * rs, sgp[c0], sbetap[c0]), 0.0f);
            float h1 = fmaxf(fmaf(d1 * rs, sgp[c1], sbetap[c1]), 0.0f);
            float h2 = fmaxf(fmaf(d2 * rs, sgp[c2], sbetap[c2]), 0.0f);

            __syncwarp();   // prior iteration's hb readers done
            hb[c0] = h0; hb[c1] = h1; hb[c2] = h2;
            __syncwarp();

            // peb = h @ Wp2 + bp2   (dominant matvec)
            float b00=0,b01=0,b02=0,b03=0, b10=0,b11=0,b12=0,b13=0, b20=0,b21=0,b22=0,b23=0;
#pragma unroll
            for (int j4 = 0; j4 < 24; j4++) {
                float4 hv = hb4[j4];
                float4 u0 = W0[j4];
                b00 = fmaf(u0.x, hv.x, b00); b01 = fmaf(u0.y, hv.y, b01);
                b02 = fmaf(u0.z, hv.z, b02); b03 = fmaf(u0.w, hv.w, b03);
                float4 u1 = W1[j4];
                b10 = fmaf(u1.x, hv.x, b10); b11 = fmaf(u1.y, hv.y, b11);
                b12 = fmaf(u1.z, hv.z, b12); b13 = fmaf(u1.w, hv.w, b13);
                float4 u2 = W2[j4];
                b20 = fmaf(u2.x, hv.x, b20); b21 = fmaf(u2.y, hv.y, b21);
                b22 = fmaf(u2.z, hv.z, b22); b23 = fmaf(u2.w, hv.w, b23);
            }
            float peb0 = b00 + b01 + b02 + b03 + sbp2[c0];
            float peb1 = b10 + b11 + b12 + b13 + sbp2[c1];
            float peb2 = b20 + b21 + b22 + b23 + sbp2[c2];

            float rel0 = kg0 * mk - qrow[c0] + peb0;
            float rel1 = kg1 * mk - qrow[c1] + peb1;
            float rel2 = kg2 * mk - qrow[c2] + peb2;
            vp[s * 96 + c0] = vg0 * mk + peb0;
            vp[s * 96 + c1] = vg1 * mk + peb1;
            vp[s * 96 + c2] = vg2 * mk + peb2;

            __syncwarp();
            hb[c0] = rel0; hb[c1] = rel1; hb[c2] = rel2;
            __syncwarp();

            // u = rel @ Ww1 + bw1  (12 outputs on lanes 0..11)
            float uacc = 0.0f;
            if (lane < 12) {
                const float4* Wg = (const float4*)(Ww1t + lane * 100);
                float s0 = 0, s1 = 0, s2 = 0, s3 = 0;
#pragma unroll
                for (int j4 = 0; j4 < 24; j4++) {
                    float4 rv = hb4[j4];
                    float4 wv = Wg[j4];
                    s0 = fmaf(wv.x, rv.x, s0); s1 = fmaf(wv.y, rv.y, s1);
                    s2 = fmaf(wv.z, rv.z, s2); s3 = fmaf(wv.w, rv.w, s3);
                }
                uacc = s0 + s1 + s2 + s3 + sbw1[lane];
            }
            // LN over G=12 (lanes 12..15 contribute zeros in the 16-lane group)
            float mug = group_sum16(uacc) * (1.0f / 12.0f);
            float eg = (lane < 12) ? (uacc - mug) * (uacc - mug) : 0.0f;
            float varg = group_sum16(eg) * (1.0f / 12.0f);
            float rsg = rsqrtf(varg + EPSF);
            float aval = 0.0f;
            if (lane < 12)
                aval = fmaxf(fmaf((uacc - mug) * rsg, sgw[lane], sbetaw[lane]), 0.0f);
            int gg = (lane < 12) ? lane : 0;
            float wlacc = sbw2[gg];
#pragma unroll
            for (int hh = 0; hh < 12; hh++) {
                float av = __shfl_sync(0xffffffffu, aval, hh);
                wlacc = fmaf(av, sWw2[hh * 12 + gg], wlacc);
            }
            if (lane < 12) wlog[s * 12 + lane] = wlacc;
            if (lane == 0) mbuf[s] = mk;
        }
        __syncthreads();

        // softmax over neighbors (per group), then * mask — matches reference order
        if (tid < 12) {
            int g = tid;
            float m = -1e30f;
#pragma unroll
            for (int s = 0; s < SNBR; s++) m = fmaxf(m, wlog[s * 12 + g]);
            float e[SNBR]; float sumv = 0.0f;
#pragma unroll
            for (int s = 0; s < SNBR; s++) { e[s] = expf(wlog[s * 12 + g] - m); sumv += e[s]; }
            float inv = 1.0f / sumv;
#pragma unroll
            for (int s = 0; s < SNBR; s++) wlog[s * 12 + g] = e[s] * inv * mbuf[s];
        }
        __syncthreads();

        // feat[n, c] = sum_s vp[s, c] * w[s, c/8]
        if (tid < 96) {
            int c = tid, g = c >> 3;
            float acc = 0.0f;
#pragma unroll
            for (int s = 0; s < SNBR; s++)
                acc = fmaf(vp[s * 96 + c], wlog[s * 12 + g], acc);
            out[n * CDIM + c] = acc;
        }
    }
}

// ---------------------------------------------------------------------------
extern "C" void kernel_launch(void* const* d_in, const int* in_sizes, int n_in,
                              void* d_out, int out_size) {
    const float* q     = (const float*)d_in[0];
    const float* k     = (const float*)d_in[1];
    const float* v     = (const float*)d_in[2];
    const float* xyz   = (const float*)d_in[3];
    const int*   ridx  = (const int*)  d_in[4];
    const float* Wq    = (const float*)d_in[5];
    const float* bq    = (const float*)d_in[6];
    const float* gq    = (const float*)d_in[7];
    const float* betaq = (const float*)d_in[8];
    const float* Wk    = (const float*)d_in[9];
    const float* bk    = (const float*)d_in[10];
    const float* gk    = (const float*)d_in[11];
    const float* betak = (const float*)d_in[12];
    const float* Wv    = (const float*)d_in[13];
    const float* bv    = (const float*)d_in[14];
    const float* Wp1   = (const float*)d_in[15];
    const float* bp1   = (const float*)d_in[16];
    const float* gp    = (const float*)d_in[17];
    const float* betap = (const float*)d_in[18];
    const float* Wp2   = (const float*)d_in[19];
    const float* bp2   = (const float*)d_in[20];
    const float* Ww1   = (const float*)d_in[21];
    const float* bw1   = (const float*)d_in[22];
    const float* gw    = (const float*)d_in[23];
    const float* betaw = (const float*)d_in[24];
    const float* Ww2   = (const float*)d_in[25];
    const float* bw2   = (const float*)d_in[26];
    float* out = (float*)d_out;

    size_t smemA = (size_t)(28800 + 672 + 768) * sizeof(float);   // 120,960 B
    size_t smemB = (size_t)SMEMB_FLOATS * sizeof(float);          //  55,552 B
    cudaFuncSetAttribute(proj_kernel, cudaFuncAttributeMaxDynamicSharedMemorySize, (int)smemA);
    cudaFuncSetAttribute(attn_kernel, cudaFuncAttributeMaxDynamicSharedMemorySize, (int)smemB);

    proj_kernel<<<152, 256, smemA>>>(q, k, v, Wq, bq, gq, betaq, Wk, bk, gk, betak, Wv, bv);
    attn_kernel<<<608, 128, smemB>>>(xyz, ridx, Wp1, bp1, gp, betap, Wp2, bp2,
                                     Ww1, bw1, gw, betaw, Ww2, bw2, out);
}

// round 4
// speedup vs baseline: 2.0509x; 2.0509x over previous
#include <cuda_runtime.h>
#include <math.h>

#define NPTS 40000
#define SNBR 16
#define CDIM 96
#define GDIM 12
#define EPSF 1e-5f

// Scratch for projected features (device globals: no allocation allowed)
__device__ float g_query[NPTS * CDIM];
__device__ float g_keyf [NPTS * CDIM];
__device__ float g_val  [NPTS * CDIM];

__device__ __forceinline__ float warp_sum32(float v) {
    v += __shfl_xor_sync(0xffffffffu, v, 16);
    v += __shfl_xor_sync(0xffffffffu, v, 8);
    v += __shfl_xor_sync(0xffffffffu, v, 4);
    v += __shfl_xor_sync(0xffffffffu, v, 2);
    v += __shfl_xor_sync(0xffffffffu, v, 1);
    return v;
}
__device__ __forceinline__ float group_sum16(float v) {
    v += __shfl_xor_sync(0xffffffffu, v, 8);
    v += __shfl_xor_sync(0xffffffffu, v, 4);
    v += __shfl_xor_sync(0xffffffffu, v, 2);
    v += __shfl_xor_sync(0xffffffffu, v, 1);
    return v;
}
__device__ __forceinline__ float d4(float4 u, float4 x, float a) {
    return fmaf(u.x, x.x, fmaf(u.y, x.y, fmaf(u.z, x.z, fmaf(u.w, x.w, a))));
}

// ---------------------------------------------------------------------------
// Kernel A: fused q/k/v projections, 4 rows per warp per batch so each
// weight LDS.128 feeds 4 FMAs.
// ---------------------------------------------------------------------------
template <bool DO_LN>
__device__ __forceinline__ void proj_batch4(
    const float* __restrict__ src, float* __restrict__ dst,
    const float* Wt,            // smem, [c][100]
    const float* bias, const float* gain, const float* beta, // smem
    float* xb,                  // per-warp smem stage, 4*96 floats
    int base, int lane)
{
    const int c0 = lane, c1 = lane + 32, c2 = lane + 64;
    bool ok[4];
#pragma unroll
    for (int r = 0; r < 4; r++) {
        int row = base + r;
        ok[r] = row < NPTS;
        if (ok[r]) {
            xb[r * 96 + c0] = src[row * CDIM + c0];
            xb[r * 96 + c1] = src[row * CDIM + c1];
            xb[r * 96 + c2] = src[row * CDIM + c2];
        }
    }
    __syncwarp();
    const float4* xb4 = (const float4*)xb;
    const float4* W0 = (const float4*)(Wt + c0 * 100);
    const float4* W1 = (const float4*)(Wt + c1 * 100);
    const float4* W2 = (const float4*)(Wt + c2 * 100);
    float a0[4] = {0,0,0,0}, a1[4] = {0,0,0,0}, a2[4] = {0,0,0,0};
#pragma unroll
    for (int j4 = 0; j4 < 24; j4++) {
        float4 x0 = xb4[j4], x1 = xb4[24 + j4], x2 = xb4[48 + j4], x3 = xb4[72 + j4];
        float4 u = W0[j4];
        a0[0] = d4(u, x0, a0[0]); a0[1] = d4(u, x1, a0[1]);
        a0[2] = d4(u, x2, a0[2]); a0[3] = d4(u, x3, a0[3]);
        u = W1[j4];
        a1[0] = d4(u, x0, a1[0]); a1[1] = d4(u, x1, a1[1]);
        a1[2] = d4(u, x2, a1[2]); a1[3] = d4(u, x3, a1[3]);
        u = W2[j4];
        a2[0] = d4(u, x0, a2[0]); a2[1] = d4(u, x1, a2[1]);
        a2[2] = d4(u, x2, a2[2]); a2[3] = d4(u, x3, a2[3]);
    }
    __syncwarp();   // readers of xb done before caller restages
#pragma unroll
    for (int r = 0; r < 4; r++) {
        float y0 = a0[r] + bias[c0];
        float y1 = a1[r] + bias[c1];
        float y2 = a2[r] + bias[c2];
        if (DO_LN) {
            float mu = warp_sum32(y0 + y1 + y2) * (1.0f / 96.0f);
            float e0 = y0 - mu, e1 = y1 - mu, e2 = y2 - mu;
            float var = warp_sum32(e0*e0 + e1*e1 + e2*e2) * (1.0f / 96.0f);
            float rs = rsqrtf(var + EPSF);
            y0 = fmaxf(fmaf(e0 * rs, gain[c0], beta[c0]), 0.0f);
            y1 = fmaxf(fmaf(e1 * rs, gain[c1], beta[c1]), 0.0f);
            y2 = fmaxf(fmaf(e2 * rs, gain[c2], beta[c2]), 0.0f);
        }
        if (ok[r]) {
            int row = base + r;
            dst[row * CDIM + c0] = y0;
            dst[row * CDIM + c1] = y1;
            dst[row * CDIM + c2] = y2;
        }
    }
}

__global__ void __launch_bounds__(256, 1) proj_kernel(
    const float* __restrict__ q, const float* __restrict__ k, const float* __restrict__ v,
    const float* __restrict__ Wq, const float* __restrict__ bq,
    const float* __restrict__ gq, const float* __restrict__ betaq,
    const float* __restrict__ Wk, const float* __restrict__ bk,
    const float* __restrict__ gk, const float* __restrict__ betak,
    const float* __restrict__ Wv, const float* __restrict__ bv)
{
    extern __shared__ float sm[];
    float* Wt  = sm;                // 3 * 9600
    float* prm = sm + 28800;        // 672
    float* xst = sm + 29472;        // 8 warps * 384

    int tid = threadIdx.x;
    for (int i = tid; i < 9216; i += blockDim.x) {
        int j = i / 96, c = i % 96;
        Wt[0 * 9600 + c * 100 + j] = Wq[i];
        Wt[1 * 9600 + c * 100 + j] = Wk[i];
        Wt[2 * 9600 + c * 100 + j] = Wv[i];
    }
    for (int i = tid; i < 96; i += blockDim.x) {
        prm[i]       = bq[i];  prm[96 + i]  = gq[i];  prm[192 + i] = betaq[i];
        prm[288 + i] = bk[i];  prm[384 + i] = gk[i];  prm[480 + i] = betak[i];
        prm[576 + i] = bv[i];
    }
    __syncthreads();

    int warp = tid >> 5, lane = tid & 31;
    int gw = blockIdx.x * 8 + warp;
    int nw = gridDim.x * 8;
    float* xb = xst + warp * 384;

    for (int base = gw * 4; base < NPTS; base += nw * 4) {
        proj_batch4<true >(q, g_query, Wt,         prm,       prm + 96,  prm + 192, xb, base, lane);
        proj_batch4<true >(k, g_keyf,  Wt + 9600,  prm + 288, prm + 384, prm + 480, xb, base, lane);
        proj_batch4<false>(v, g_val,   Wt + 19200, prm + 576, prm,       prm,       xb, base, lane);
    }
}

// ---------------------------------------------------------------------------
// Kernel B: fused grouped vector attention. 4 warps, 4 neighbors each,
// batched matvecs so every weight LDS feeds 4 FMAs.
// ---------------------------------------------------------------------------
#define OFF_WP2T   0        // 9600  ([c][100])
#define OFF_WW1T   9600     // 1200  ([g][100])
#define OFF_WP1    10800    // 288
#define OFF_BP1    11088    // 96
#define OFF_GP     11184    // 96
#define OFF_BETAP  11280    // 96
#define OFF_BP2    11376    // 96
#define OFF_WW2    11472    // 144
#define OFF_BW1    11616    // 12
#define OFF_GW     11628    // 12
#define OFF_BETAW  11640    // 12
#define OFF_BW2    11652    // 12
#define OFF_QROW   11664    // 96
#define OFF_WLOG   11760    // 192
#define OFF_MBUF   11952    // 16
#define OFF_HBUF   11968    // 4*384  (h, then rel, then partial feat)
#define SMEMB_FLOATS 13504

__global__ void __launch_bounds__(128, 4) attn_kernel(
    const float* __restrict__ xyz, const int* __restrict__ refidx,
    const float* __restrict__ Wp1, const float* __restrict__ bp1,
    const float* __restrict__ gp,  const float* __restrict__ betap,
    const float* __restrict__ Wp2, const float* __restrict__ bp2,
    const float* __restrict__ Ww1, const float* __restrict__ bw1,
    const float* __restrict__ gw,  const float* __restrict__ betaw,
    const float* __restrict__ Ww2, const float* __restrict__ bw2,
    float* __restrict__ out)
{
    extern __shared__ float sm[];
    float* Wp2t  = sm + OFF_WP2T;
    float* Ww1t  = sm + OFF_WW1T;
    float* sWp1  = sm + OFF_WP1;
    float* sbp1  = sm + OFF_BP1;
    float* sgp   = sm + OFF_GP;
    float* sbetap= sm + OFF_BETAP;
    float* sbp2  = sm + OFF_BP2;
    float* sWw2  = sm + OFF_WW2;
    float* sbw1  = sm + OFF_BW1;
    float* sgw   = sm + OFF_GW;
    float* sbetaw= sm + OFF_BETAW;
    float* sbw2  = sm + OFF_BW2;
    float* qrow  = sm + OFF_QROW;
    float* wlog  = sm + OFF_WLOG;
    float* mbuf  = sm + OFF_MBUF;
    float* hbuf  = sm + OFF_HBUF;

    int tid = threadIdx.x;
    for (int i = tid; i < 9216; i += blockDim.x) {
        int j = i / 96, c = i % 96;
        Wp2t[c * 100 + j] = Wp2[i];
    }
    for (int i = tid; i < 1152; i += blockDim.x) {
        int j = i / 12, g = i % 12;
        Ww1t[g * 100 + j] = Ww1[i];
    }
    for (int i = tid; i < 288; i += blockDim.x) sWp1[i] = Wp1[i];
    for (int i = tid; i < 96; i += blockDim.x) {
        sbp1[i] = bp1[i]; sgp[i] = gp[i]; sbetap[i] = betap[i]; sbp2[i] = bp2[i];
    }
    for (int i = tid; i < 144; i += blockDim.x) sWw2[i] = Ww2[i];
    if (tid < 12) { sbw1[tid] = bw1[tid]; sgw[tid] = gw[tid]; sbetaw[tid] = betaw[tid]; sbw2[tid] = bw2[tid]; }
    __syncthreads();

    int warp = tid >> 5, lane = tid & 31;
    const int c0 = lane, c1 = lane + 32, c2 = lane + 64;
    float* hb = hbuf + warp * 384;
    const float4* hb4 = (const float4*)hb;
    const float4* W0 = (const float4*)(Wp2t + c0 * 100);
    const float4* W1 = (const float4*)(Wp2t + c1 * 100);
    const float4* W2 = (const float4*)(Wp2t + c2 * 100);

    // hoist per-lane loop invariants
    float w1_00 = sWp1[c0],       w1_10 = sWp1[96 + c0], w1_20 = sWp1[192 + c0];
    float w1_01 = sWp1[c1],       w1_11 = sWp1[96 + c1], w1_21 = sWp1[192 + c1];
    float w1_02 = sWp1[c2],       w1_12 = sWp1[96 + c2], w1_22 = sWp1[192 + c2];
    float bb0 = sbp1[c0],  bb1 = sbp1[c1],  bb2 = sbp1[c2];
    float gp0 = sgp[c0],   gp1 = sgp[c1],   gp2 = sgp[c2];
    float be0 = sbetap[c0],be1 = sbetap[c1],be2 = sbetap[c2];
    float b20 = sbp2[c0],  b21 = sbp2[c1],  b22 = sbp2[c2];
    const int g0 = c0 >> 3, g1 = c1 >> 3, g2 = c2 >> 3;
    const int sbase = warp * 4;
    const int halfbit = lane & 16;
    const int gl = lane & 15;
    const bool act = gl < 12;

    for (int n = blockIdx.x; n < NPTS; n += gridDim.x) {
        __syncthreads();   // previous point fully consumed
        if (tid < 96) qrow[tid] = g_query[n * CDIM + tid];
        __syncthreads();
        float qr0 = qrow[c0], qr1 = qrow[c1], qr2 = qrow[c2];

        float px = xyz[n * 3], py = xyz[n * 3 + 1], pz = xyz[n * 3 + 2];

        // gathers first: long-latency L2 loads in flight during matvecs
        float mk[4]; int safe[4];
        float kg0[4], kg1[4], kg2[4], vg0[4], vg1[4], vg2[4];
#pragma unroll
        for (int ss = 0; ss < 4; ss++) {
            int idx = refidx[n * SNBR + sbase + ss];
            mk[ss] = (idx >= 0) ? 1.0f : 0.0f;
            int sf = (idx >= 0) ? idx : 0;
            safe[ss] = sf;
            kg0[ss] = g_keyf[sf * CDIM + c0];
            kg1[ss] = g_keyf[sf * CDIM + c1];
            kg2[ss] = g_keyf[sf * CDIM + c2];
            vg0[ss] = g_val [sf * CDIM + c0];
            vg1[ss] = g_val [sf * CDIM + c1];
            vg2[ss] = g_val [sf * CDIM + c2];
        }
        if (lane == 0) {
#pragma unroll
            for (int ss = 0; ss < 4; ss++) mbuf[sbase + ss] = mk[ss];
        }

        // phase 1: h = relu(ln(pos@Wp1+bp1)) for 4 neighbors -> hb
#pragma unroll
        for (int ss = 0; ss < 4; ss++) {
            int sf = safe[ss]; float m = mk[ss];
            float p0 = (xyz[sf * 3]     - px) * m;
            float p1 = (xyz[sf * 3 + 1] - py) * m;
            float p2 = (xyz[sf * 3 + 2] - pz) * m;
            float t0 = fmaf(p0, w1_00, fmaf(p1, w1_10, fmaf(p2, w1_20, bb0)));
            float t1 = fmaf(p0, w1_01, fmaf(p1, w1_11, fmaf(p2, w1_21, bb1)));
            float t2 = fmaf(p0, w1_02, fmaf(p1, w1_12, fmaf(p2, w1_22, bb2)));
            float mu = warp_sum32(t0 + t1 + t2) * (1.0f / 96.0f);
            float e0 = t0 - mu, e1 = t1 - mu, e2 = t2 - mu;
            float var = warp_sum32(e0*e0 + e1*e1 + e2*e2) * (1.0f / 96.0f);
            float rs = rsqrtf(var + EPSF);
            hb[ss * 96 + c0] = fmaxf(fmaf(e0 * rs, gp0, be0), 0.0f);
            hb[ss * 96 + c1] = fmaxf(fmaf(e1 * rs, gp1, be1), 0.0f);
            hb[ss * 96 + c2] = fmaxf(fmaf(e2 * rs, gp2, be2), 0.0f);
        }
        __syncwarp();

        // phase 2: batched peb matvec (weight reuse x4)
        float a0[4] = {0,0,0,0}, a1[4] = {0,0,0,0}, a2[4] = {0,0,0,0};
#pragma unroll
        for (int j4 = 0; j4 < 24; j4++) {
            float4 h0 = hb4[j4], h1 = hb4[24 + j4], h2 = hb4[48 + j4], h3 = hb4[72 + j4];
            float4 u = W0[j4];
            a0[0] = d4(u, h0, a0[0]); a0[1] = d4(u, h1, a0[1]);
            a0[2] = d4(u, h2, a0[2]); a0[3] = d4(u, h3, a0[3]);
            u = W1[j4];
            a1[0] = d4(u, h0, a1[0]); a1[1] = d4(u, h1, a1[1]);
            a1[2] = d4(u, h2, a1[2]); a1[3] = d4(u, h3, a1[3]);
            u = W2[j4];
            a2[0] = d4(u, h0, a2[0]); a2[1] = d4(u, h1, a2[1]);
            a2[2] = d4(u, h2, a2[2]); a2[3] = d4(u, h3, a2[3]);
        }
        __syncwarp();   // hb reads done before rel overwrite

        float vp0[4], vp1[4], vp2[4];
#pragma unroll
        for (int ss = 0; ss < 4; ss++) {
            float m = mk[ss];
            float peb0 = a0[ss] + b20, peb1 = a1[ss] + b21, peb2 = a2[ss] + b22;
            hb[ss * 96 + c0] = fmaf(kg0[ss], m, -qr0) + peb0;
            hb[ss * 96 + c1] = fmaf(kg1[ss], m, -qr1) + peb1;
            hb[ss * 96 + c2] = fmaf(kg2[ss], m, -qr2) + peb2;
            vp0[ss] = fmaf(vg0[ss], m, peb0);
            vp1[ss] = fmaf(vg1[ss], m, peb1);
            vp2[ss] = fmaf(vg2[ss], m, peb2);
        }
        __syncwarp();

        // phase 3: w-logits, both half-warps active, 2 neighbors per pass
#pragma unroll
        for (int pass = 0; pass < 2; pass++) {
            int sl = pass * 2 + (halfbit >> 4);
            float u0 = 0, u1 = 0, u2 = 0, u3 = 0;
            if (act) {
                const float4* Wg = (const float4*)(Ww1t + gl * 100);
                const float4* rv = hb4 + sl * 24;
#pragma unroll
                for (int j4 = 0; j4 < 24; j4++) {
                    float4 r = rv[j4], w = Wg[j4];
                    u0 = fmaf(w.x, r.x, u0); u1 = fmaf(w.y, r.y, u1);
                    u2 = fmaf(w.z, r.z, u2); u3 = fmaf(w.w, r.w, u3);
                }
            }
            float uacc = act ? (u0 + u1 + u2 + u3 + sbw1[gl]) : 0.0f;
            float mug = group_sum16(uacc) * (1.0f / 12.0f);
            float df = act ? (uacc - mug) : 0.0f;
            float varg = group_sum16(df * df) * (1.0f / 12.0f);
            float rsg = rsqrtf(varg + EPSF);
            float aval = act ? fmaxf(fmaf(df * rsg, sgw[gl], sbetaw[gl]), 0.0f) : 0.0f;
            int gg = act ? gl : 0;
            float wl = sbw2[gg];
#pragma unroll
            for (int hh = 0; hh < 12; hh++) {
                float av = __shfl_sync(0xffffffffu, aval, halfbit | hh);
                wl = fmaf(av, sWw2[hh * 12 + gg], wl);
            }
            if (act) wlog[(sbase + sl) * 12 + gl] = wl;
        }
        __syncthreads();

        // softmax over neighbors per group, * mask
        if (tid < 12) {
            int g = tid;
            float m = -1e30f;
#pragma unroll
            for (int s = 0; s < SNBR; s++) m = fmaxf(m, wlog[s * 12 + g]);
            float e[SNBR]; float sumv = 0.0f;
#pragma unroll
            for (int s = 0; s < SNBR; s++) { e[s] = expf(wlog[s * 12 + g] - m); sumv += e[s]; }
            float inv = 1.0f / sumv;
#pragma unroll
            for (int s = 0; s < SNBR; s++) wlog[s * 12 + g] = e[s] * inv * mbuf[s];
        }
        __syncthreads();

        // phase 4: per-warp partial einsum, then block sum
        float f0 = 0, f1 = 0, f2 = 0;
#pragma unroll
        for (int ss = 0; ss < 4; ss++) {
            f0 = fmaf(vp0[ss], wlog[(sbase + ss) * 12 + g0], f0);
            f1 = fmaf(vp1[ss], wlog[(sbase + ss) * 12 + g1], f1);
            f2 = fmaf(vp2[ss], wlog[(sbase + ss) * 12 + g2], f2);
        }
        hb[c0] = f0; hb[c1] = f1; hb[c2] = f2;   // reuse hbuf as partial buffer
        __syncthreads();
        if (tid < 96)
            out[n * CDIM + tid] = hbuf[tid] + hbuf[384 + tid] + hbuf[768 + tid] + hbuf[1152 + tid];
    }
}

// ---------------------------------------------------------------------------
extern "C" void kernel_launch(void* const* d_in, const int* in_sizes, int n_in,
                              void* d_out, int out_size) {
    const float* q     = (const float*)d_in[0];
    const float* k     = (const float*)d_in[1];
    const float* v     = (const float*)d_in[2];
    const float* xyz   = (const float*)d_in[3];
    const int*   ridx  = (const int*)  d_in[4];
    const float* Wq    = (const float*)d_in[5];
    const float* bq    = (const float*)d_in[6];
    const float* gq    = (const float*)d_in[7];
    const float* betaq = (const float*)d_in[8];
    const float* Wk    = (const float*)d_in[9];
    const float* bk    = (const float*)d_in[10];
    const float* gk    = (const float*)d_in[11];
    const float* betak = (const float*)d_in[12];
    const float* Wv    = (const float*)d_in[13];
    const float* bv    = (const float*)d_in[14];
    const float* Wp1   = (const float*)d_in[15];
    const float* bp1   = (const float*)d_in[16];
    const float* gp    = (const float*)d_in[17];
    const float* betap = (const float*)d_in[18];
    const float* Wp2   = (const float*)d_in[19];
    const float* bp2   = (const float*)d_in[20];
    const float* Ww1   = (const float*)d_in[21];
    const float* bw1   = (const float*)d_in[22];
    const float* gw    = (const float*)d_in[23];
    const float* betaw = (const float*)d_in[24];
    const float* Ww2   = (const float*)d_in[25];
    const float* bw2   = (const float*)d_in[26];
    float* out = (float*)d_out;

    size_t smemA = (size_t)(28800 + 672 + 8 * 384) * sizeof(float);   // ~130 KB
    size_t smemB = (size_t)SMEMB_FLOATS * sizeof(float);              // ~54 KB
    cudaFuncSetAttribute(proj_kernel, cudaFuncAttributeMaxDynamicSharedMemorySize, (int)smemA);
    cudaFuncSetAttribute(attn_kernel, cudaFuncAttributeMaxDynamicSharedMemorySize, (int)smemB);

    proj_kernel<<<152, 256, smemA>>>(q, k, v, Wq, bq, gq, betaq, Wk, bk, gk, betak, Wv, bv);
    attn_kernel<<<592, 128, smemB>>>(xyz, ridx, Wp1, bp1, gp, betap, Wp2, bp2,
                                     Ww1, bw1, gw, betaw, Ww2, bw2, out);
}